// round 1
// baseline (speedup 1.0000x reference)
#include <cuda_runtime.h>
#include <math.h>

// Problem constants (fixed dataset: B=2048, S=64, H=256, n_steps=32)
#define BB      2048
#define HH      256
#define SS      64
#define NSTEPS  32
#define N4      1024          // 4*H
#define PS      ((NSTEPS+1)*HH) // prediction row stride = 33*256

// GEMM tiling
#define BM 128
#define BN 128
#define BK 16

// ---------------- scratch (static device globals; no allocs allowed) -------
__device__ float g_h[2][BB*HH];      // ping-pong hidden state
__device__ float g_c[BB*HH];         // cell state (in-place, owner-exclusive)
__device__ float g_Wih_t[HH*N4];     // W_ih^T, gate-interleaved columns
__device__ float g_Whh_t[HH*N4];     // W_hh^T, gate-interleaved
__device__ float g_Wc_t [HH*N4];     // (W_ih+W_hh)^T, for AR steps (x==h)
__device__ float g_bias [N4];        // b_ih + b_hh, gate-interleaved

// ---------------- one-time prep: transpose + gate-interleave + zero state --
// Column n = 4*j + g  <->  original row = g*H + j   (PyTorch i,f,g,o layout)
__global__ void init_kernel(const float* __restrict__ W_ih,
                            const float* __restrict__ W_hh,
                            const float* __restrict__ b_ih,
                            const float* __restrict__ b_hh)
{
    int i = blockIdx.x * blockDim.x + threadIdx.x;     // up to BB*HH
    if (i < BB*HH) { g_h[0][i] = 0.f; g_c[i] = 0.f; }
    if (i < HH*N4) {
        int k = i / N4, n = i % N4;
        int j = n >> 2, g = n & 3;
        int orig = g * HH + j;
        float a = W_ih[orig*HH + k];
        float b = W_hh[orig*HH + k];
        g_Wih_t[i] = a; g_Whh_t[i] = b; g_Wc_t[i] = a + b;
    }
    if (i < N4) {
        int j = i >> 2, g = i & 3;
        int orig = g * HH + j;
        g_bias[i] = b_ih[orig] + b_hh[orig];
    }
}

__device__ __forceinline__ float sigmoidf_(float x) {
    return 1.0f / (1.0f + __expf(-x));
}

// One K=256 GEMM pass: acc[8][8] += A[BMxK] tile-row * W[KxN4] tile-col
// A is row-major with row stride `astride`; W is row-major [HH][N4].
__device__ __forceinline__ void gemm_pass(
    float acc[8][8],
    const float* __restrict__ A, int astride,
    const float* __restrict__ W,
    int bm, int bn, int tid,
    float As[BK][BM], float Bs[BK][BN])
{
    const int ra = (tid >> 4) * 4;   // thread row base (and +64 for 2nd group)
    const int ca = (tid & 15) * 4;   // thread col base (and +64 for 2nd group)

    for (int k0 = 0; k0 < HH; k0 += BK) {
        // load A tile [BM x BK] transposed into As[BK][BM]
        #pragma unroll
        for (int l = 0; l < 2; l++) {
            int idx = tid + l * 256;           // 0..511
            int row = idx >> 2;                // 0..127
            int kv  = (idx & 3) << 2;          // 0,4,8,12
            float4 v = *(const float4*)(A + (size_t)(bm*BM + row) * astride + k0 + kv);
            As[kv+0][row] = v.x; As[kv+1][row] = v.y;
            As[kv+2][row] = v.z; As[kv+3][row] = v.w;
        }
        // load W tile [BK x BN] directly
        #pragma unroll
        for (int l = 0; l < 2; l++) {
            int idx = tid + l * 256;           // 0..511
            int kr  = idx >> 5;                // 0..15
            int nv  = (idx & 31) << 2;         // 0..124
            *(float4*)(&Bs[kr][nv]) =
                *(const float4*)(W + (size_t)(k0 + kr) * N4 + bn*BN + nv);
        }
        __syncthreads();

        #pragma unroll
        for (int k = 0; k < BK; k++) {
            float a[8], b[8];
            #pragma unroll
            for (int i = 0; i < 4; i++) { a[i]   = As[k][ra + i];
                                          a[i+4] = As[k][ra + 64 + i]; }
            #pragma unroll
            for (int j = 0; j < 4; j++) { b[j]   = Bs[k][ca + j];
                                          b[j+4] = Bs[k][ca + 64 + j]; }
            #pragma unroll
            for (int i = 0; i < 8; i++)
                #pragma unroll
                for (int j = 0; j < 8; j++)
                    acc[i][j] = fmaf(a[i], b[j], acc[i][j]);
        }
        __syncthreads();
    }
}

// Fused GEMM + LSTM cell. ENC: gates = h@Whh_t + x@Wih_t ; AR: gates = h@Wc_t.
// Columns are gate-interleaved, so each 4-col group = one h-unit's (i,f,g,o).
template<bool ENC>
__global__ void __launch_bounds__(256, 1)
lstm_step_kernel(const float* __restrict__ xA, int xStride, int sel,
                 float* __restrict__ pred)
{
    __shared__ float As[BK][BM];
    __shared__ float Bs[BK][BN];
    const int tid = threadIdx.x;
    const int bn  = blockIdx.x;    // 0..7   (N4/BN)
    const int bm  = blockIdx.y;    // 0..15  (BB/BM)

    float acc[8][8];
    #pragma unroll
    for (int i = 0; i < 8; i++)
        #pragma unroll
        for (int j = 0; j < 8; j++) acc[i][j] = 0.f;

    const float* h_in  = g_h[sel];
    float*       h_out = g_h[sel ^ 1];

    gemm_pass(acc, h_in, HH, ENC ? g_Whh_t : g_Wc_t, bm, bn, tid, As, Bs);
    if (ENC)
        gemm_pass(acc, xA, xStride, g_Wih_t, bm, bn, tid, As, Bs);

    // ---- fused LSTM cell epilogue ----
    const int ra = (tid >> 4) * 4;
    const int ca = (tid & 15) * 4;
    const int gr_base = bm*BM + ra;

    float bv[8];
    #pragma unroll
    for (int c = 0; c < 8; c++)
        bv[c] = g_bias[bn*BN + ca + (c >> 2)*64 + (c & 3)];

    #pragma unroll
    for (int i = 0; i < 8; i++) {
        int row = gr_base + ((i < 4) ? i : (i - 4 + 64));
        #pragma unroll
        for (int jg = 0; jg < 2; jg++) {
            float iv = sigmoidf_(acc[i][jg*4+0] + bv[jg*4+0]);
            float fv = sigmoidf_(acc[i][jg*4+1] + bv[jg*4+1]);
            float gv = tanhf    (acc[i][jg*4+2] + bv[jg*4+2]);
            float ov = sigmoidf_(acc[i][jg*4+3] + bv[jg*4+3]);
            int   j  = ((bn*BN + ca + jg*64) >> 2);   // h-unit index
            size_t idx = (size_t)row * HH + j;
            float cn = fmaf(fv, g_c[idx], iv * gv);
            float hn = ov * tanhf(cn);
            g_c[idx]   = cn;
            h_out[idx] = hn;
            if (pred) pred[(size_t)row * PS + j] = hn;
        }
    }
}

extern "C" void kernel_launch(void* const* d_in, const int* in_sizes, int n_in,
                              void* d_out, int out_size)
{
    const float* x0   = (const float*)d_in[0];   // [B, S, H]
    const float* W_ih = (const float*)d_in[1];   // [4H, H]
    const float* W_hh = (const float*)d_in[2];   // [4H, H]
    const float* b_ih = (const float*)d_in[3];   // [4H]
    const float* b_hh = (const float*)d_in[4];   // [4H]
    float* out = (float*)d_out;                  // [B, 33, H]
    (void)in_sizes; (void)n_in; (void)out_size;

    init_kernel<<<(BB*HH + 255)/256, 256>>>(W_ih, W_hh, b_ih, b_hh);

    dim3 grid(N4/BN, BB/BM);   // (8, 16) = 128 CTAs: one clean wave on 148 SMs
    int sel = 0;

    // Encode: 64 steps; last one writes prediction slot 0 (h after encode).
    for (int t = 0; t < SS; t++) {
        float* pred = (t == SS - 1) ? out : nullptr;
        lstm_step_kernel<true><<<grid, 256>>>(x0 + (size_t)t * HH, SS * HH, sel, pred);
        sel ^= 1;
    }
    // Autoregressive rollout: x == h  =>  combined weights, slots 1..32.
    for (int t = 0; t < NSTEPS; t++) {
        lstm_step_kernel<false><<<grid, 256>>>(nullptr, 0, sel,
                                               out + (size_t)(t + 1) * HH);
        sel ^= 1;
    }
}

// round 3
// speedup vs baseline: 1.7642x; 1.7642x over previous
#include <cuda_runtime.h>
#include <cuda_bf16.h>
#include <cstdint>

// Fixed problem: B=2048, S=64, H=256, n_steps=32
#define BB 2048
#define HH 256
#define SS 64
#define NSTEPS 32
#define N4 1024
#define PS ((NSTEPS+1)*HH)

#define TILE_B 16384                 // 128 rows x 64 bf16 cols (128B rows)
#define STAGE_B (4*TILE_B)           // A_hi, A_lo, W_hi, W_lo
#define SMEM_BYTES (2*STAGE_B)       // 128 KB double-buffered

// ---------------- static device scratch ------------------------------------
__device__ uint32_t g_h_hi[2][BB*HH/2];   // packed bf16 pairs (j even/odd)
__device__ uint32_t g_h_lo[2][BB*HH/2];
__device__ __nv_bfloat16 g_x_hi[(size_t)BB*SS*HH];
__device__ __nv_bfloat16 g_x_lo[(size_t)BB*SS*HH];
__device__ __nv_bfloat16 g_Whh_hi[N4*HH], g_Whh_lo[N4*HH];
__device__ __nv_bfloat16 g_Wih_hi[N4*HH], g_Wih_lo[N4*HH];
__device__ __nv_bfloat16 g_Wc_hi [N4*HH], g_Wc_lo [N4*HH];
__device__ float g_bias[N4];

// ---------------- small helpers ---------------------------------------------
__device__ __forceinline__ uint32_t smem_u32(const void* p) {
    uint32_t a;
    asm("{ .reg .u64 t; cvta.to.shared.u64 t, %1; cvt.u32.u64 %0, t; }" : "=r"(a) : "l"(p));
    return a;
}
__device__ __forceinline__ uint32_t swz(uint32_t b) { return b ^ ((b >> 3) & 0x70u); }

__device__ __forceinline__ void cp16(uint32_t d, const void* s) {
    asm volatile("cp.async.cg.shared.global [%0], [%1], 16;" :: "r"(d), "l"(s) : "memory");
}
#define CP_COMMIT() asm volatile("cp.async.commit_group;" ::: "memory")
#define CP_WAIT1()  asm volatile("cp.async.wait_group 1;" ::: "memory")
#define CP_WAIT0()  asm volatile("cp.async.wait_group 0;" ::: "memory")

__device__ __forceinline__ void ldsm4(uint32_t& r0, uint32_t& r1, uint32_t& r2, uint32_t& r3,
                                      uint32_t a) {
    asm volatile("ldmatrix.sync.aligned.m8n8.x4.shared.b16 {%0,%1,%2,%3}, [%4];"
                 : "=r"(r0), "=r"(r1), "=r"(r2), "=r"(r3) : "r"(a));
}
__device__ __forceinline__ void mma16816(float* c, const uint32_t* a, const uint32_t* b) {
    asm volatile("mma.sync.aligned.m16n8k16.row.col.f32.bf16.bf16.f32 "
                 "{%0,%1,%2,%3}, {%4,%5,%6,%7}, {%8,%9}, {%0,%1,%2,%3};"
                 : "+f"(c[0]), "+f"(c[1]), "+f"(c[2]), "+f"(c[3])
                 : "r"(a[0]), "r"(a[1]), "r"(a[2]), "r"(a[3]), "r"(b[0]), "r"(b[1]));
}

__device__ __forceinline__ void bsplit(float v, __nv_bfloat16& hi, __nv_bfloat16& lo) {
    __nv_bfloat16 h = __float2bfloat16(v);
    hi = h;
    lo = __float2bfloat16(v - __bfloat162float(h));
}
__device__ __forceinline__ float sigf(float x) {
    return __fdividef(1.0f, 1.0f + __expf(-x));
}
__device__ __forceinline__ float tanhf_(float x) {
    float cx = fminf(fmaxf(x, -15.0f), 15.0f);
    float e  = __expf(2.0f * cx);
    return __fdividef(e - 1.0f, e + 1.0f);
}

// ---------------- init kernels ----------------------------------------------
// Gate column permutation: col n -> gate=(n>>3)&3, unit j=(n>>7)*32+((n>>5)&3)*8+(n&7)
__global__ void init_weights(const float* __restrict__ W_ih, const float* __restrict__ W_hh,
                             const float* __restrict__ b_ih, const float* __restrict__ b_hh)
{
    int i = blockIdx.x * blockDim.x + threadIdx.x;
    if (i >= N4 * HH) return;
    int n = i / HH, k = i % HH;
    int gate = (n >> 3) & 3;
    int j    = (n >> 7) * 32 + ((n >> 5) & 3) * 8 + (n & 7);
    int orig = gate * HH + j;
    float a = W_ih[orig * HH + k];
    float b = W_hh[orig * HH + k];
    bsplit(a,     g_Wih_hi[i], g_Wih_lo[i]);
    bsplit(b,     g_Whh_hi[i], g_Whh_lo[i]);
    bsplit(a + b, g_Wc_hi[i],  g_Wc_lo[i]);
    if (k == 0) g_bias[n] = b_ih[orig] + b_hh[orig];
    // zero initial hidden state (i happens to cover exactly BB*HH/2 = 262144)
    if (i < BB * HH / 2) { g_h_hi[0][i] = 0u; g_h_lo[0][i] = 0u; }
}
__global__ void init_x(const float* __restrict__ x0)
{
    size_t i = (size_t)blockIdx.x * blockDim.x + threadIdx.x;
    if (i < (size_t)BB * SS * HH) bsplit(x0[i], g_x_hi[i], g_x_lo[i]);
}

// ---------------- persistent fused LSTM kernel ------------------------------
__global__ void __launch_bounds__(256, 1) __cluster_dims__(8, 1, 1)
lstm_persist(float* __restrict__ out)
{
    extern __shared__ char smem[];
    const uint32_t sb = smem_u32(smem);
    const int tid  = threadIdx.x;
    const int wid  = tid >> 5, lane = tid & 31;
    const int bn   = blockIdx.x;          // 0..7 (cluster rank)
    const int bm   = blockIdx.y;          // 0..15
    const int wm   = wid >> 2, wn = wid & 3;

    // per-thread constant bias: gates x 2 units
    float bias_r[4][2];
    #pragma unroll
    for (int g = 0; g < 4; g++)
        #pragma unroll
        for (int qq = 0; qq < 2; qq++)
            bias_r[g][qq] = g_bias[bn * 128 + wn * 32 + g * 8 + (lane & 3) * 2 + qq];

    float creg[16];
    #pragma unroll
    for (int i = 0; i < 16; i++) creg[i] = 0.0f;

    int sel = 0;

    for (int step = 0; step < SS + NSTEPS; step++) {
        const bool enc = (step < SS);
        const int  nch = enc ? 8 : 4;

        float acc[4][4][4];
        #pragma unroll
        for (int a = 0; a < 4; a++)
            #pragma unroll
            for (int b = 0; b < 4; b++)
                #pragma unroll
                for (int r = 0; r < 4; r++) acc[a][b][r] = 0.0f;

        // ---- chunk loader (lambda-ish via macro-free inline) ----
        auto load_chunk = [&](int buf, int c) {
            const __nv_bfloat16 *ahi, *alo, *whi, *wlo;
            size_t astr; int kc;
            if (enc && c >= 4) {
                ahi = g_x_hi + (size_t)step * HH;
                alo = g_x_lo + (size_t)step * HH;
                astr = (size_t)SS * HH; kc = (c - 4) * 64;
                whi = g_Wih_hi; wlo = g_Wih_lo;
            } else {
                ahi = (const __nv_bfloat16*)g_h_hi[sel];
                alo = (const __nv_bfloat16*)g_h_lo[sel];
                astr = HH; kc = c * 64;
                whi = enc ? g_Whh_hi : g_Wc_hi;
                wlo = enc ? g_Whh_lo : g_Wc_lo;
            }
            const uint32_t st = sb + buf * STAGE_B;
            #pragma unroll
            for (int i = 0; i < 4; i++) {
                int id = tid + i * 256;          // 0..1023
                int r  = id >> 3, cb = id & 7;   // row, 16B-chunk
                uint32_t so = swz((uint32_t)r * 128u + (uint32_t)cb * 16u);
                cp16(st + 0 * TILE_B + so, ahi + (size_t)(bm * 128 + r) * astr + kc + cb * 8);
                cp16(st + 1 * TILE_B + so, alo + (size_t)(bm * 128 + r) * astr + kc + cb * 8);
                cp16(st + 2 * TILE_B + so, whi + (size_t)(bn * 128 + r) * HH   + kc + cb * 8);
                cp16(st + 3 * TILE_B + so, wlo + (size_t)(bn * 128 + r) * HH   + kc + cb * 8);
            }
        };

        load_chunk(0, 0);
        CP_COMMIT();

        for (int c = 0; c < nch; c++) {
            if (c + 1 < nch) { load_chunk((c + 1) & 1, c + 1); CP_COMMIT(); CP_WAIT1(); }
            else             { CP_WAIT0(); }
            __syncthreads();

            const uint32_t aH = sb + (c & 1) * STAGE_B;
            const uint32_t aL = aH + TILE_B;
            const uint32_t wH = aH + 2 * TILE_B;
            const uint32_t wL = aH + 3 * TILE_B;

            #pragma unroll
            for (int ks = 0; ks < 4; ks++) {
                // B fragments: 4 gate-frags hi + lo, via 2 x4-ldmatrix each
                uint32_t bh[4][2], bl[4][2];
                {
                    const int gsel = lane >> 3;                       // 0..3
                    const int nloc = wn * 32 + (gsel >> 1) * 8 + (lane & 7);
                    const int kb   = ks * 32 + (gsel & 1) * 16;
                    uint32_t o01 = swz((uint32_t)nloc * 128u + kb);
                    uint32_t o23 = swz((uint32_t)(nloc + 16) * 128u + kb);
                    ldsm4(bh[0][0], bh[0][1], bh[1][0], bh[1][1], wH + o01);
                    ldsm4(bh[2][0], bh[2][1], bh[3][0], bh[3][1], wH + o23);
                    ldsm4(bl[0][0], bl[0][1], bl[1][0], bl[1][1], wL + o01);
                    ldsm4(bl[2][0], bl[2][1], bl[3][0], bl[3][1], wL + o23);
                }
                #pragma unroll
                for (int mf = 0; mf < 4; mf++) {
                    const int rloc = wm * 64 + mf * 16 + (lane & 15);
                    const int kb   = ks * 32 + (lane >> 4) * 16;
                    uint32_t ao = swz((uint32_t)rloc * 128u + kb);
                    uint32_t ah[4], al[4];
                    ldsm4(ah[0], ah[1], ah[2], ah[3], aH + ao);
                    ldsm4(al[0], al[1], al[2], al[3], aL + ao);
                    #pragma unroll
                    for (int g = 0; g < 4; g++) {
                        mma16816(acc[mf][g], ah, bh[g]);
                        mma16816(acc[mf][g], ah, bl[g]);
                        mma16816(acc[mf][g], al, bh[g]);
                    }
                }
            }
            __syncthreads();
        }

        // ---- fused LSTM epilogue (c in registers, gates per-thread) ----
        const int  slot   = enc ? 0 : (step - SS + 1);
        const bool wrpred = (!enc) || (step == SS - 1);
        uint32_t* hhi = g_h_hi[sel ^ 1];
        uint32_t* hlo = g_h_lo[sel ^ 1];

        #pragma unroll
        for (int mf = 0; mf < 4; mf++) {
            #pragma unroll
            for (int rr = 0; rr < 2; rr++) {
                float hv[2];
                #pragma unroll
                for (int qq = 0; qq < 2; qq++) {
                    const int ridx = rr * 2 + qq;
                    float iv = sigf  (acc[mf][0][ridx] + bias_r[0][qq]);
                    float fv = sigf  (acc[mf][1][ridx] + bias_r[1][qq]);
                    float gv = tanhf_(acc[mf][2][ridx] + bias_r[2][qq]);
                    float ov = sigf  (acc[mf][3][ridx] + bias_r[3][qq]);
                    const int ci = mf * 4 + rr * 2 + qq;
                    creg[ci] = fmaf(fv, creg[ci], iv * gv);
                    hv[qq] = ov * tanhf_(creg[ci]);
                }
                const int row = bm * 128 + wm * 64 + mf * 16 + (lane >> 2) + rr * 8;
                const int j   = bn * 32 + wn * 8 + (lane & 3) * 2;
                __nv_bfloat16 h0, l0, h1, l1;
                bsplit(hv[0], h0, l0);
                bsplit(hv[1], h1, l1);
                const uint32_t hi32 = (uint32_t)__bfloat16_as_ushort(h0) |
                                      ((uint32_t)__bfloat16_as_ushort(h1) << 16);
                const uint32_t lo32 = (uint32_t)__bfloat16_as_ushort(l0) |
                                      ((uint32_t)__bfloat16_as_ushort(l1) << 16);
                const int hidx = row * (HH / 2) + (j >> 1);
                hhi[hidx] = hi32;
                hlo[hidx] = lo32;
                if (wrpred) {
                    float2 p = make_float2(hv[0], hv[1]);
                    *(float2*)&out[(size_t)row * PS + (size_t)slot * HH + j] = p;
                }
            }
        }

        sel ^= 1;
        asm volatile("barrier.cluster.arrive.aligned;" ::: "memory");
        asm volatile("barrier.cluster.wait.aligned;"   ::: "memory");
    }
}

// ---------------- launch ------------------------------------------------------
extern "C" void kernel_launch(void* const* d_in, const int* in_sizes, int n_in,
                              void* d_out, int out_size)
{
    const float* x0   = (const float*)d_in[0];
    const float* W_ih = (const float*)d_in[1];
    const float* W_hh = (const float*)d_in[2];
    const float* b_ih = (const float*)d_in[3];
    const float* b_hh = (const float*)d_in[4];
    float* out = (float*)d_out;
    (void)in_sizes; (void)n_in; (void)out_size;

    cudaFuncSetAttribute(lstm_persist,
                         cudaFuncAttributeMaxDynamicSharedMemorySize, SMEM_BYTES);

    init_weights<<<(N4 * HH + 255) / 256, 256>>>(W_ih, W_hh, b_ih, b_hh);
    init_x<<<(int)(((size_t)BB * SS * HH + 255) / 256), 256>>>(x0);

    dim3 grid(8, 16);   // 128 CTAs = 16 clusters of 8 (one cluster per bm group)
    lstm_persist<<<grid, 256, SMEM_BYTES>>>(out);
}

// round 4
// speedup vs baseline: 2.2994x; 1.3034x over previous
#include <cuda_runtime.h>
#include <cuda_fp16.h>
#include <cstdint>

// Fixed problem: B=2048, S=64, H=256, n_steps=32
#define BB 2048
#define HH 256
#define SS 64
#define NSTEPS 32
#define N4 1024
#define PS ((NSTEPS+1)*HH)

#define TILE_B 16384                 // 128 rows x 64 fp16 cols (128B rows)
#define STAGE_B (3*TILE_B)           // A_hi, A_lo, W
#define SMEM_BYTES (2*STAGE_B)       // 96 KB double-buffered

// ---------------- static device scratch ------------------------------------
__device__ uint32_t g_h_hi[2][BB*HH/2];   // packed fp16 pairs (unit j even/odd)
__device__ uint32_t g_h_lo[2][BB*HH/2];
__device__ __half g_x_hi[(size_t)BB*SS*HH];
__device__ __half g_x_lo[(size_t)BB*SS*HH];
__device__ __half g_Whh[N4*HH];
__device__ __half g_Wih[N4*HH];
__device__ __half g_Wc [N4*HH];
__device__ float g_bias[N4];

// ---------------- small helpers ---------------------------------------------
__device__ __forceinline__ uint32_t smem_u32(const void* p) {
    uint32_t a;
    asm("{ .reg .u64 t; cvta.to.shared.u64 t, %1; cvt.u32.u64 %0, t; }" : "=r"(a) : "l"(p));
    return a;
}
__device__ __forceinline__ uint32_t swz(uint32_t b) { return b ^ ((b >> 3) & 0x70u); }

__device__ __forceinline__ void cp16(uint32_t d, const void* s) {
    asm volatile("cp.async.cg.shared.global [%0], [%1], 16;" :: "r"(d), "l"(s) : "memory");
}
#define CP_COMMIT() asm volatile("cp.async.commit_group;" ::: "memory")
#define CP_WAIT1()  asm volatile("cp.async.wait_group 1;" ::: "memory")
#define CP_WAIT0()  asm volatile("cp.async.wait_group 0;" ::: "memory")

__device__ __forceinline__ void ldsm4(uint32_t& r0, uint32_t& r1, uint32_t& r2, uint32_t& r3,
                                      uint32_t a) {
    asm volatile("ldmatrix.sync.aligned.m8n8.x4.shared.b16 {%0,%1,%2,%3}, [%4];"
                 : "=r"(r0), "=r"(r1), "=r"(r2), "=r"(r3) : "r"(a));
}
__device__ __forceinline__ void mma16816(float* c, const uint32_t* a, const uint32_t* b) {
    asm volatile("mma.sync.aligned.m16n8k16.row.col.f32.f16.f16.f32 "
                 "{%0,%1,%2,%3}, {%4,%5,%6,%7}, {%8,%9}, {%0,%1,%2,%3};"
                 : "+f"(c[0]), "+f"(c[1]), "+f"(c[2]), "+f"(c[3])
                 : "r"(a[0]), "r"(a[1]), "r"(a[2]), "r"(a[3]), "r"(b[0]), "r"(b[1]));
}

__device__ __forceinline__ void hsplit(float v, __half& hi, __half& lo) {
    __half h = __float2half_rn(v);
    hi = h;
    lo = __float2half_rn(v - __half2float(h));
}
__device__ __forceinline__ float sigf(float x) {
    return __fdividef(1.0f, 1.0f + __expf(-x));
}
__device__ __forceinline__ float tanhf_(float x) {
    float cx = fminf(fmaxf(x, -15.0f), 15.0f);
    float e  = __expf(2.0f * cx);
    return __fdividef(e - 1.0f, e + 1.0f);
}

// ---------------- init kernels ----------------------------------------------
// Gate column permutation: col n -> gate=(n>>3)&3, unit j=(n>>7)*32+((n>>5)&3)*8+(n&7)
__global__ void init_weights(const float* __restrict__ W_ih, const float* __restrict__ W_hh,
                             const float* __restrict__ b_ih, const float* __restrict__ b_hh)
{
    int i = blockIdx.x * blockDim.x + threadIdx.x;
    if (i >= N4 * HH) return;
    int n = i / HH, k = i % HH;
    int gate = (n >> 3) & 3;
    int j    = (n >> 7) * 32 + ((n >> 5) & 3) * 8 + (n & 7);
    int orig = gate * HH + j;
    float a = W_ih[orig * HH + k];
    float b = W_hh[orig * HH + k];
    g_Wih[i] = __float2half_rn(a);
    g_Whh[i] = __float2half_rn(b);
    g_Wc [i] = __float2half_rn(a + b);
    if (k == 0) g_bias[n] = b_ih[orig] + b_hh[orig];
    // zero initial hidden state (i covers exactly BB*HH/2 = 262144)
    if (i < BB * HH / 2) { g_h_hi[0][i] = 0u; g_h_lo[0][i] = 0u; }
}
__global__ void init_x(const float* __restrict__ x0)
{
    size_t i = (size_t)blockIdx.x * blockDim.x + threadIdx.x;
    if (i < (size_t)BB * SS * HH) hsplit(x0[i], g_x_hi[i], g_x_lo[i]);
}

// ---------------- persistent fused LSTM kernel ------------------------------
__global__ void __launch_bounds__(256, 1) __cluster_dims__(8, 1, 1)
lstm_persist(float* __restrict__ out)
{
    extern __shared__ char smem[];
    const uint32_t sb = smem_u32(smem);
    const int tid  = threadIdx.x;
    const int wid  = tid >> 5, lane = tid & 31;
    const int bn   = blockIdx.x;          // 0..7 (cluster rank)
    const int bm   = blockIdx.y;          // 0..15
    const int wm   = wid >> 2, wn = wid & 3;

    // per-thread constant bias: gates x 2 units
    float bias_r[4][2];
    #pragma unroll
    for (int g = 0; g < 4; g++)
        #pragma unroll
        for (int qq = 0; qq < 2; qq++)
            bias_r[g][qq] = g_bias[bn * 128 + wn * 32 + g * 8 + (lane & 3) * 2 + qq];

    float creg[16];
    #pragma unroll
    for (int i = 0; i < 16; i++) creg[i] = 0.0f;

    int sel = 0;

    for (int step = 0; step < SS + NSTEPS; step++) {
        const bool enc = (step < SS);
        const int  nch = enc ? 8 : 4;

        float acc[4][4][4];
        #pragma unroll
        for (int a = 0; a < 4; a++)
            #pragma unroll
            for (int b = 0; b < 4; b++)
                #pragma unroll
                for (int r = 0; r < 4; r++) acc[a][b][r] = 0.0f;

        auto load_chunk = [&](int buf, int c) {
            const __half *ahi, *alo, *w;
            size_t astr; int kc;
            if (enc && c >= 4) {
                ahi = g_x_hi + (size_t)step * HH;
                alo = g_x_lo + (size_t)step * HH;
                astr = (size_t)SS * HH; kc = (c - 4) * 64;
                w = g_Wih;
            } else {
                ahi = (const __half*)g_h_hi[sel];
                alo = (const __half*)g_h_lo[sel];
                astr = HH; kc = c * 64;
                w = enc ? g_Whh : g_Wc;
            }
            const uint32_t st = sb + buf * STAGE_B;
            #pragma unroll
            for (int i = 0; i < 4; i++) {
                int id = tid + i * 256;          // 0..1023
                int r  = id >> 3, cb = id & 7;   // row, 16B-chunk
                uint32_t so = swz((uint32_t)r * 128u + (uint32_t)cb * 16u);
                cp16(st + 0 * TILE_B + so, ahi + (size_t)(bm * 128 + r) * astr + kc + cb * 8);
                cp16(st + 1 * TILE_B + so, alo + (size_t)(bm * 128 + r) * astr + kc + cb * 8);
                cp16(st + 2 * TILE_B + so, w   + (size_t)(bn * 128 + r) * HH   + kc + cb * 8);
            }
        };

        load_chunk(0, 0);
        CP_COMMIT();

        for (int c = 0; c < nch; c++) {
            if (c + 1 < nch) { load_chunk((c + 1) & 1, c + 1); CP_COMMIT(); CP_WAIT1(); }
            else             { CP_WAIT0(); }
            __syncthreads();

            const uint32_t aH = sb + (c & 1) * STAGE_B;
            const uint32_t aL = aH + TILE_B;
            const uint32_t wB = aH + 2 * TILE_B;

            #pragma unroll
            for (int ks = 0; ks < 4; ks++) {
                // B fragments: 4 gate-frags via 2 x4-ldmatrix
                uint32_t bf[4][2];
                {
                    const int gsel = lane >> 3;                       // 0..3
                    const int nloc = wn * 32 + (gsel >> 1) * 8 + (lane & 7);
                    const int kb   = ks * 32 + (gsel & 1) * 16;
                    uint32_t o01 = swz((uint32_t)nloc * 128u + kb);
                    uint32_t o23 = swz((uint32_t)(nloc + 16) * 128u + kb);
                    ldsm4(bf[0][0], bf[0][1], bf[1][0], bf[1][1], wB + o01);
                    ldsm4(bf[2][0], bf[2][1], bf[3][0], bf[3][1], wB + o23);
                }
                #pragma unroll
                for (int mf = 0; mf < 4; mf++) {
                    const int rloc = wm * 64 + mf * 16 + (lane & 15);
                    const int kb   = ks * 32 + (lane >> 4) * 16;
                    uint32_t ao = swz((uint32_t)rloc * 128u + kb);
                    uint32_t ah[4], al[4];
                    ldsm4(ah[0], ah[1], ah[2], ah[3], aH + ao);
                    ldsm4(al[0], al[1], al[2], al[3], aL + ao);
                    #pragma unroll
                    for (int g = 0; g < 4; g++) mma16816(acc[mf][g], ah, bf[g]);
                    #pragma unroll
                    for (int g = 0; g < 4; g++) mma16816(acc[mf][g], al, bf[g]);
                }
            }
            __syncthreads();
        }

        // ---- fused LSTM epilogue (c in registers, gates per-thread) ----
        const int  slot   = enc ? 0 : (step - SS + 1);
        const bool wrpred = (!enc) || (step == SS - 1);
        uint32_t* hhi = g_h_hi[sel ^ 1];
        uint32_t* hlo = g_h_lo[sel ^ 1];

        #pragma unroll
        for (int mf = 0; mf < 4; mf++) {
            #pragma unroll
            for (int rr = 0; rr < 2; rr++) {
                float hv[2];
                #pragma unroll
                for (int qq = 0; qq < 2; qq++) {
                    const int ridx = rr * 2 + qq;
                    float iv = sigf  (acc[mf][0][ridx] + bias_r[0][qq]);
                    float fv = sigf  (acc[mf][1][ridx] + bias_r[1][qq]);
                    float gv = tanhf_(acc[mf][2][ridx] + bias_r[2][qq]);
                    float ov = sigf  (acc[mf][3][ridx] + bias_r[3][qq]);
                    const int ci = mf * 4 + rr * 2 + qq;
                    creg[ci] = fmaf(fv, creg[ci], iv * gv);
                    hv[qq] = ov * tanhf_(creg[ci]);
                }
                const int row = bm * 128 + wm * 64 + mf * 16 + (lane >> 2) + rr * 8;
                const int j   = bn * 32 + wn * 8 + (lane & 3) * 2;
                __half h0, l0, h1, l1;
                hsplit(hv[0], h0, l0);
                hsplit(hv[1], h1, l1);
                const uint32_t hi32 = (uint32_t)__half_as_ushort(h0) |
                                      ((uint32_t)__half_as_ushort(h1) << 16);
                const uint32_t lo32 = (uint32_t)__half_as_ushort(l0) |
                                      ((uint32_t)__half_as_ushort(l1) << 16);
                const int hidx = row * (HH / 2) + (j >> 1);
                hhi[hidx] = hi32;
                hlo[hidx] = lo32;
                if (wrpred) {
                    float2 p = make_float2(hv[0], hv[1]);
                    *(float2*)&out[(size_t)row * PS + (size_t)slot * HH + j] = p;
                }
            }
        }

        sel ^= 1;
        asm volatile("barrier.cluster.arrive.aligned;" ::: "memory");
        asm volatile("barrier.cluster.wait.aligned;"   ::: "memory");
    }
}

// ---------------- launch ------------------------------------------------------
extern "C" void kernel_launch(void* const* d_in, const int* in_sizes, int n_in,
                              void* d_out, int out_size)
{
    const float* x0   = (const float*)d_in[0];
    const float* W_ih = (const float*)d_in[1];
    const float* W_hh = (const float*)d_in[2];
    const float* b_ih = (const float*)d_in[3];
    const float* b_hh = (const float*)d_in[4];
    float* out = (float*)d_out;
    (void)in_sizes; (void)n_in; (void)out_size;

    cudaFuncSetAttribute(lstm_persist,
                         cudaFuncAttributeMaxDynamicSharedMemorySize, SMEM_BYTES);

    init_weights<<<(N4 * HH + 255) / 256, 256>>>(W_ih, W_hh, b_ih, b_hh);
    init_x<<<(int)(((size_t)BB * SS * HH + 255) / 256), 256>>>(x0);

    dim3 grid(8, 16);   // 128 CTAs = 16 clusters of 8 (one cluster per bm group)
    lstm_persist<<<grid, 256, SMEM_BYTES>>>(out);
}

// round 5
// speedup vs baseline: 2.8258x; 1.2290x over previous
#include <cuda_runtime.h>
#include <cuda_fp16.h>
#include <cstdint>

// Fixed problem: B=2048, S=64, H=256, n_steps=32
#define BB 2048
#define HH 256
#define SS 64
#define NSTEPS 32
#define N4 1024
#define PS ((NSTEPS+1)*HH)

#define TILE_B 16384                 // 128 rows x 64 fp16 cols, SW128 rows of 128B
#define W_BYTES (8*TILE_B)           // 128 KB: ENC = Whh[0..3] + Wih[4..7]; AR = Wc[0..3]
#define AB_OFF  W_BYTES
#define ABUF_B  (2*TILE_B)           // A_hi + A_lo
#define SMEM_BYTES (W_BYTES + 3*ABUF_B)   // 229376 B = 224 KB

// ---------------- static device scratch ------------------------------------
__device__ uint32_t g_h_hi[2][BB*HH/2];   // packed fp16 pairs (unit j even/odd)
__device__ uint32_t g_h_lo[2][BB*HH/2];
__device__ __half g_x[(size_t)BB*SS*HH];  // x at plain fp16
__device__ __half g_Whh[N4*HH];
__device__ __half g_Wih[N4*HH];
__device__ __half g_Wc [N4*HH];
__device__ float g_bias[N4];

// ---------------- small helpers ---------------------------------------------
__device__ __forceinline__ uint32_t smem_u32(const void* p) {
    uint32_t a;
    asm("{ .reg .u64 t; cvta.to.shared.u64 t, %1; cvt.u32.u64 %0, t; }" : "=r"(a) : "l"(p));
    return a;
}
__device__ __forceinline__ uint32_t swz(uint32_t b) { return b ^ ((b >> 3) & 0x70u); }

__device__ __forceinline__ void cp16(uint32_t d, const void* s) {
    asm volatile("cp.async.cg.shared.global [%0], [%1], 16;" :: "r"(d), "l"(s) : "memory");
}
#define CP_COMMIT() asm volatile("cp.async.commit_group;" ::: "memory")
#define CP_WAIT1()  asm volatile("cp.async.wait_group 1;" ::: "memory")
#define CP_WAIT0()  asm volatile("cp.async.wait_group 0;" ::: "memory")

__device__ __forceinline__ void ldsm4(uint32_t& r0, uint32_t& r1, uint32_t& r2, uint32_t& r3,
                                      uint32_t a) {
    asm volatile("ldmatrix.sync.aligned.m8n8.x4.shared.b16 {%0,%1,%2,%3}, [%4];"
                 : "=r"(r0), "=r"(r1), "=r"(r2), "=r"(r3) : "r"(a));
}
__device__ __forceinline__ void mma16816(float* c, const uint32_t* a, const uint32_t* b) {
    asm volatile("mma.sync.aligned.m16n8k16.row.col.f32.f16.f16.f32 "
                 "{%0,%1,%2,%3}, {%4,%5,%6,%7}, {%8,%9}, {%0,%1,%2,%3};"
                 : "+f"(c[0]), "+f"(c[1]), "+f"(c[2]), "+f"(c[3])
                 : "r"(a[0]), "r"(a[1]), "r"(a[2]), "r"(a[3]), "r"(b[0]), "r"(b[1]));
}

__device__ __forceinline__ void hsplit(float v, __half& hi, __half& lo) {
    __half h = __float2half_rn(v);
    hi = h;
    lo = __float2half_rn(v - __half2float(h));
}
__device__ __forceinline__ float sigf(float x) {
    return __fdividef(1.0f, 1.0f + __expf(-x));
}
__device__ __forceinline__ float tanhf_(float x) {
    float cx = fminf(fmaxf(x, -15.0f), 15.0f);
    float e  = __expf(2.0f * cx);
    return __fdividef(e - 1.0f, e + 1.0f);
}

// ---------------- single init kernel -----------------------------------------
// Gate column permutation: col n -> gate=(n>>3)&3, unit j=(n>>7)*32+((n>>5)&3)*8+(n&7)
__global__ void init_all(const float* __restrict__ x0,
                         const float* __restrict__ W_ih, const float* __restrict__ W_hh,
                         const float* __restrict__ b_ih, const float* __restrict__ b_hh)
{
    size_t i = (size_t)blockIdx.x * blockDim.x + threadIdx.x;
    if (i < (size_t)BB * SS * HH) g_x[i] = __float2half_rn(x0[i]);
    if (i < (size_t)N4 * HH) {
        int n = (int)(i / HH), k = (int)(i % HH);
        int gate = (n >> 3) & 3;
        int j    = (n >> 7) * 32 + ((n >> 5) & 3) * 8 + (n & 7);
        int orig = gate * HH + j;
        float a = W_ih[orig * HH + k];
        float b = W_hh[orig * HH + k];
        g_Wih[i] = __float2half_rn(a);
        g_Whh[i] = __float2half_rn(b);
        g_Wc [i] = __float2half_rn(a + b);
        if (k == 0) g_bias[n] = b_ih[orig] + b_hh[orig];
    }
    if (i < (size_t)BB * HH / 2) { g_h_hi[0][i] = 0u; g_h_lo[0][i] = 0u; }
}

// ---------------- per-chunk MMA body ------------------------------------------
template<bool LO>
__device__ __forceinline__ void do_chunk(float acc[4][4][4], uint32_t ab, uint32_t wb,
                                         int wm, int wn, int lane)
{
    #pragma unroll
    for (int ks = 0; ks < 4; ks++) {
        uint32_t bf[4][2];
        {
            const int gsel = lane >> 3;                       // 0..3
            const int nloc = wn * 32 + (gsel >> 1) * 8 + (lane & 7);
            const int kb   = ks * 32 + (gsel & 1) * 16;
            uint32_t o01 = swz((uint32_t)nloc * 128u + kb);
            uint32_t o23 = swz((uint32_t)(nloc + 16) * 128u + kb);
            ldsm4(bf[0][0], bf[0][1], bf[1][0], bf[1][1], wb + o01);
            ldsm4(bf[2][0], bf[2][1], bf[3][0], bf[3][1], wb + o23);
        }
        #pragma unroll
        for (int mf = 0; mf < 4; mf++) {
            const int rloc = wm * 64 + mf * 16 + (lane & 15);
            const int kb   = ks * 32 + (lane >> 4) * 16;
            uint32_t ao = swz((uint32_t)rloc * 128u + kb);
            uint32_t ah[4];
            ldsm4(ah[0], ah[1], ah[2], ah[3], ab + ao);
            #pragma unroll
            for (int g = 0; g < 4; g++) mma16816(acc[mf][g], ah, bf[g]);
            if (LO) {
                uint32_t al[4];
                ldsm4(al[0], al[1], al[2], al[3], ab + TILE_B + ao);
                #pragma unroll
                for (int g = 0; g < 4; g++) mma16816(acc[mf][g], al, bf[g]);
            }
        }
    }
}

// ---------------- persistent fused LSTM kernel ------------------------------
__global__ void __launch_bounds__(256, 1) __cluster_dims__(8, 1, 1)
lstm_persist(float* __restrict__ out)
{
    extern __shared__ char smem[];
    const uint32_t sb = smem_u32(smem);
    const int tid  = threadIdx.x;
    const int wid  = tid >> 5, lane = tid & 31;
    const int bn   = blockIdx.x;          // 0..7 (cluster rank)
    const int bm   = blockIdx.y;          // 0..15
    const int wm   = wid >> 2, wn = wid & 3;

    float bias_r[4][2];
    #pragma unroll
    for (int g = 0; g < 4; g++)
        #pragma unroll
        for (int qq = 0; qq < 2; qq++)
            bias_r[g][qq] = g_bias[bn * 128 + wn * 32 + g * 8 + (lane & 3) * 2 + qq];

    float creg[16];
    #pragma unroll
    for (int i = 0; i < 16; i++) creg[i] = 0.0f;

    int sel = 0;

    for (int step = 0; step < SS + NSTEPS; step++) {
        const bool enc = (step < SS);
        const int  nch = enc ? 8 : 4;

        float acc[4][4][4];
        #pragma unroll
        for (int a = 0; a < 4; a++)
            #pragma unroll
            for (int b = 0; b < 4; b++)
                #pragma unroll
                for (int r = 0; r < 4; r++) acc[a][b][r] = 0.0f;

        // ---- A-chunk loader (W lives in smem permanently) ----
        auto load_a = [&](int c) {
            const uint32_t ab = sb + AB_OFF + (c % 3) * ABUF_B;
            if (enc && c >= 4) {
                const __half* x = g_x + (size_t)step * HH + (size_t)(c - 4) * 64;
                #pragma unroll
                for (int i = 0; i < 4; i++) {
                    int id = tid + i * 256;
                    int r  = id >> 3, cb = id & 7;
                    uint32_t so = swz((uint32_t)r * 128u + (uint32_t)cb * 16u);
                    cp16(ab + so, x + (size_t)(bm * 128 + r) * (SS * HH) + cb * 8);
                }
            } else {
                const __half* hh_ = (const __half*)g_h_hi[sel];
                const __half* hl_ = (const __half*)g_h_lo[sel];
                const int kc = c * 64;
                #pragma unroll
                for (int i = 0; i < 4; i++) {
                    int id = tid + i * 256;
                    int r  = id >> 3, cb = id & 7;
                    uint32_t so = swz((uint32_t)r * 128u + (uint32_t)cb * 16u);
                    cp16(ab + so,          hh_ + (size_t)(bm * 128 + r) * HH + kc + cb * 8);
                    cp16(ab + TILE_B + so, hl_ + (size_t)(bm * 128 + r) * HH + kc + cb * 8);
                }
            }
        };

        // One-time W loads (grouped with chunk-0's cp group)
        if (step == 0) {
            #pragma unroll
            for (int i = 0; i < 32; i++) {
                int t  = i >> 2;                       // tile 0..7
                int id = tid + (i & 3) * 256;
                int r  = id >> 3, cb = id & 7;
                const __half* w = (t < 4) ? g_Whh : g_Wih;
                int kc = (t & 3) * 64;
                uint32_t so = swz((uint32_t)r * 128u + (uint32_t)cb * 16u);
                cp16(sb + t * TILE_B + so, w + (size_t)(bn * 128 + r) * HH + kc + cb * 8);
            }
        } else if (step == SS) {
            #pragma unroll
            for (int i = 0; i < 16; i++) {
                int t  = i >> 2;                       // tile 0..3 <- W_c
                int id = tid + (i & 3) * 256;
                int r  = id >> 3, cb = id & 7;
                int kc = t * 64;
                uint32_t so = swz((uint32_t)r * 128u + (uint32_t)cb * 16u);
                cp16(sb + t * TILE_B + so, g_Wc + (size_t)(bn * 128 + r) * HH + kc + cb * 8);
            }
        }
        load_a(0);
        CP_COMMIT();

        for (int c = 0; c < nch; c++) {
            if (c + 1 < nch) { load_a(c + 1); CP_COMMIT(); CP_WAIT1(); }
            else             { CP_WAIT0(); }
            __syncthreads();

            const uint32_t ab = sb + AB_OFF + (c % 3) * ABUF_B;
            const uint32_t wb = sb + c * TILE_B;
            if (enc && c >= 4) do_chunk<false>(acc, ab, wb, wm, wn, lane);
            else               do_chunk<true >(acc, ab, wb, wm, wn, lane);
        }

        // ---- fused LSTM epilogue ----
        const int  slot   = enc ? 0 : (step - SS + 1);
        const bool wrpred = (!enc) || (step == SS - 1);
        uint32_t* hhi = g_h_hi[sel ^ 1];
        uint32_t* hlo = g_h_lo[sel ^ 1];

        float hv_all[16];
        #pragma unroll
        for (int mf = 0; mf < 4; mf++) {
            #pragma unroll
            for (int rr = 0; rr < 2; rr++) {
                float hv[2];
                #pragma unroll
                for (int qq = 0; qq < 2; qq++) {
                    const int ridx = rr * 2 + qq;
                    float iv = sigf  (acc[mf][0][ridx] + bias_r[0][qq]);
                    float fv = sigf  (acc[mf][1][ridx] + bias_r[1][qq]);
                    float gv = tanhf_(acc[mf][2][ridx] + bias_r[2][qq]);
                    float ov = sigf  (acc[mf][3][ridx] + bias_r[3][qq]);
                    const int ci = mf * 4 + rr * 2 + qq;
                    creg[ci] = fmaf(fv, creg[ci], iv * gv);
                    hv[qq] = ov * tanhf_(creg[ci]);
                    hv_all[ci] = hv[qq];
                }
                const int row = bm * 128 + wm * 64 + mf * 16 + (lane >> 2) + rr * 8;
                const int j   = bn * 32 + wn * 8 + (lane & 3) * 2;
                __half h0, l0, h1, l1;
                hsplit(hv[0], h0, l0);
                hsplit(hv[1], h1, l1);
                const uint32_t hi32 = (uint32_t)__half_as_ushort(h0) |
                                      ((uint32_t)__half_as_ushort(h1) << 16);
                const uint32_t lo32 = (uint32_t)__half_as_ushort(l0) |
                                      ((uint32_t)__half_as_ushort(l1) << 16);
                const int hidx = row * (HH / 2) + (j >> 1);
                hhi[hidx] = hi32;
                hlo[hidx] = lo32;
            }
        }
        // h is published; arrive early, overlap pred stores with peer skew.
        asm volatile("barrier.cluster.arrive.aligned;" ::: "memory");
        if (wrpred) {
            #pragma unroll
            for (int mf = 0; mf < 4; mf++)
                #pragma unroll
                for (int rr = 0; rr < 2; rr++) {
                    const int row = bm * 128 + wm * 64 + mf * 16 + (lane >> 2) + rr * 8;
                    const int j   = bn * 32 + wn * 8 + (lane & 3) * 2;
                    float2 p = make_float2(hv_all[mf * 4 + rr * 2 + 0],
                                           hv_all[mf * 4 + rr * 2 + 1]);
                    *(float2*)&out[(size_t)row * PS + (size_t)slot * HH + j] = p;
                }
        }
        sel ^= 1;
        asm volatile("barrier.cluster.wait.aligned;" ::: "memory");
    }
}

// ---------------- launch ------------------------------------------------------
extern "C" void kernel_launch(void* const* d_in, const int* in_sizes, int n_in,
                              void* d_out, int out_size)
{
    const float* x0   = (const float*)d_in[0];
    const float* W_ih = (const float*)d_in[1];
    const float* W_hh = (const float*)d_in[2];
    const float* b_ih = (const float*)d_in[3];
    const float* b_hh = (const float*)d_in[4];
    float* out = (float*)d_out;
    (void)in_sizes; (void)n_in; (void)out_size;

    cudaFuncSetAttribute(lstm_persist,
                         cudaFuncAttributeMaxDynamicSharedMemorySize, SMEM_BYTES);

    init_all<<<(int)(((size_t)BB * SS * HH + 255) / 256), 256>>>(x0, W_ih, W_hh, b_ih, b_hh);

    dim3 grid(8, 16);   // 128 CTAs = 16 clusters of 8 (one cluster per bm group)
    lstm_persist<<<grid, 256, SMEM_BYTES>>>(out);
}